// round 4
// baseline (speedup 1.0000x reference)
#include <cuda_runtime.h>
#include <math.h>

// grid_layer: spherical neighborhood projection onto a 4x8 (dist,theta) grid.
// x (1,N,16) f32, coordinates (2,N) f32, sigma_d (1,), kappa_vm (1,),
// local_indices (1,N) i32, adjc (N,7) i32  ->  out (1,N,4,8,16) f32.
//
// One warp per node, lane = d*8 + t. Lanes 0..6 compute great-circle
// (dist, phi) once; shfl-broadcast. CRITICAL: the atan2 second argument is
// computed with explicitly-rounded muls (no FMA contraction) so that the
// degenerate center-vs-itself case gives atan2(+0,+0) = +0, matching XLA's
// separately-rounded elementwise lowering. With FMA it becomes the rounding
// error of fl(s1*c1) with random sign; the negative half flips phi to +pi
// and anti-phases the von-Mises weights (the observed rel_err = sqrt(1/7)).

#define PI_F 3.14159265358979323846f
#define FULL 0xffffffffu

__global__ __launch_bounds__(256) void grid_layer_kernel(
    const float* __restrict__ x,
    const float* __restrict__ coords,      // [2, N]
    const float* __restrict__ sigma_d_p,   // scalar
    const float* __restrict__ kappa_p,     // scalar
    const int*   __restrict__ local_indices,
    const int*   __restrict__ adjc,        // [N, 7]
    float*       __restrict__ out,         // [N, 4, 8, 16]
    int N)
{
    const int warp = threadIdx.x >> 5;
    const int lane = threadIdx.x & 31;
    const int node = blockIdx.x * 8 + warp;
    if (node >= N) return;

    const int li = __ldg(&local_indices[node]);

    // lanes 0..6 hold one neighbor each
    int idxk = 0;
    if (lane < 7) idxk = __ldg(&adjc[li * 7 + lane]);
    const int idx0 = __shfl_sync(FULL, idxk, 0);

    float dval = 0.0f, pval = 0.0f;
    if (lane < 7) {
        const float lon1 = __ldg(&coords[idx0]);
        const float lat1 = __ldg(&coords[N + idx0]);
        const float lon2 = __ldg(&coords[idxk]);
        const float lat2 = __ldg(&coords[N + idxk]);
        const float dlon = lon2 - lon1;

        const float s1 = sinf(lat1), c1 = cosf(lat1);
        const float s2 = sinf(lat2), c2 = cosf(lat2);
        const float sd = sinf(dlon), cd = cosf(dlon);

        // cos_d = s1*s2 + (c1*c2)*cd  -- separately rounded, like XLA
        float cosd = __fadd_rn(__fmul_rn(s1, s2),
                               __fmul_rn(__fmul_rn(c1, c2), cd));
        cosd = fminf(fmaxf(cosd, -1.0f + 1e-7f), 1.0f - 1e-7f);
        dval = acosf(cosd);

        // y = c1*s2 - (s1*c2)*cd  -- separately rounded: exact +0 when
        // lat2==lat1 && dlon==0, so atan2(+0,+0) = +0 (matches reference).
        const float yy = __fsub_rn(__fmul_rn(c1, s2),
                                   __fmul_rn(__fmul_rn(s1, c2), cd));
        const float xx = __fmul_rn(sd, c2);
        pval = atan2f(xx, yy);
    }

    // broadcast dist/phi for all 7 neighbors to every lane
    float dist[7], phi[7];
#pragma unroll
    for (int k = 0; k < 7; k++) {
        dist[k] = __shfl_sync(FULL, dval, k);
        phi[k]  = __shfl_sync(FULL, pval, k);
    }

    const float sigma = __ldg(&sigma_d_p[0]);
    const float kappa = __ldg(&kappa_p[0]);

    // this lane's (d, t) cell
    const int d_i = lane >> 3;
    const int t_i = lane & 7;
    const float dp    = (float)d_i * (0.2f / 3.0f);          // linspace(0,0.2,4)
    const float theta = -PI_F + (float)t_i * (PI_F * 0.25f); // linspace(-pi,pi,9)[:-1]

    float w[7];
    float sum = 0.0f;
#pragma unroll
    for (int k = 0; k < 7; k++) {
        const float z  = (dp - dist[k]) / sigma;
        const float vm = expf(kappa * cosf(theta - phi[k]));
        const float nd = expf(-0.5f * (z * z));
        w[k] = vm * nd;
        sum += w[k];
    }
    const float inv = 1.0f / (sum + 1e-10f);

    // weighted feature sum: warp-uniform gathers -> L1 broadcast
    float4 a0 = make_float4(0.f, 0.f, 0.f, 0.f);
    float4 a1 = a0, a2 = a0, a3 = a0;
#pragma unroll
    for (int k = 0; k < 7; k++) {
        const int xi = __shfl_sync(FULL, idxk, k);
        const float wk = w[k] * inv;
        const float4* row = reinterpret_cast<const float4*>(x + (size_t)xi * 16);
        const float4 v0 = __ldg(row + 0);
        const float4 v1 = __ldg(row + 1);
        const float4 v2 = __ldg(row + 2);
        const float4 v3 = __ldg(row + 3);
        a0.x += wk * v0.x; a0.y += wk * v0.y; a0.z += wk * v0.z; a0.w += wk * v0.w;
        a1.x += wk * v1.x; a1.y += wk * v1.y; a1.z += wk * v1.z; a1.w += wk * v1.w;
        a2.x += wk * v2.x; a2.y += wk * v2.y; a2.z += wk * v2.z; a2.w += wk * v2.w;
        a3.x += wk * v3.x; a3.y += wk * v3.y; a3.z += wk * v3.z; a3.w += wk * v3.w;
    }

    // coalesced contiguous write: out[node*512 + lane*16 .. +16]
    float* o = out + (size_t)node * 512 + (size_t)lane * 16;
    reinterpret_cast<float4*>(o)[0] = a0;
    reinterpret_cast<float4*>(o)[1] = a1;
    reinterpret_cast<float4*>(o)[2] = a2;
    reinterpret_cast<float4*>(o)[3] = a3;
}

extern "C" void kernel_launch(void* const* d_in, const int* in_sizes, int n_in,
                              void* d_out, int out_size) {
    // out is (1, N, 4, 8, 16) -> N = out_size / 512 (exact).
    const int N = out_size / 512;

    // Bind inputs by element count (robust to metadata ordering).
    const float* x       = 0;
    const float* coords  = 0;
    const float* sigma_d = 0;
    const float* kappa   = 0;
    const int*   lidx    = 0;
    const int*   adjc    = 0;
    int n_scalar = 0;
    for (int i = 0; i < n_in; i++) {
        const int s = in_sizes[i];
        if (s == 1) {
            if (n_scalar++ == 0) sigma_d = (const float*)d_in[i];
            else                 kappa   = (const float*)d_in[i];
        } else if (s == N)        lidx   = (const int*)d_in[i];
        else if (s == 2 * N)      coords = (const float*)d_in[i];
        else if (s == 7 * N)      adjc   = (const int*)d_in[i];
        else if (s == 16 * N)     x      = (const float*)d_in[i];
    }

    float* out = (float*)d_out;
    const int blocks = (N + 7) / 8;  // 8 warps/block, 1 warp/node
    grid_layer_kernel<<<blocks, 256>>>(x, coords, sigma_d, kappa,
                                       lidx, adjc, out, N);
}

// round 8
// speedup vs baseline: 1.1290x; 1.1290x over previous
#include <cuda_runtime.h>
#include <math.h>

// grid_layer split into two kernels:
//  K1: per-(node,neighbor) great-circle (dist, phi), precise math, full lane
//      utilization, float2 results in __device__ scratch. Separately-rounded
//      products so the degenerate self-pair gives atan2(+0,+0)=+0 (bit-matches
//      the XLA reference; FMA contraction here caused the sqrt(1/7) failure).
//  K2: per-node warp computes 4x8 fused fast-math weights, gathers 7x16
//      features (warp-uniform -> L1 broadcast), writes 2KB contiguous.

#define PI_F 3.14159265358979323846f
#define FULL 0xffffffffu
#define MAXN 65536

__device__ float2 g_dp[MAXN * 7];   // (dist, phi) per (node, neighbor)

// ---------------- Kernel 1: precise trig, one thread per (node, k) ----------
__global__ __launch_bounds__(256) void trig_kernel(
    const float* __restrict__ coords,      // [2, N]
    const int*   __restrict__ local_indices,
    const int*   __restrict__ adjc,        // [N, 7]
    int N)
{
    const int t = blockIdx.x * 256 + threadIdx.x;
    if (t >= N * 7) return;
    const int node = t / 7;
    const int k    = t - node * 7;

    const int li   = __ldg(&local_indices[node]);
    const int idx0 = __ldg(&adjc[li * 7]);
    const int idxk = __ldg(&adjc[li * 7 + k]);

    const float lon1 = __ldg(&coords[idx0]);
    const float lat1 = __ldg(&coords[N + idx0]);
    const float lon2 = __ldg(&coords[idxk]);
    const float lat2 = __ldg(&coords[N + idxk]);
    const float dlon = lon2 - lon1;

    const float s1 = sinf(lat1), c1 = cosf(lat1);
    const float s2 = sinf(lat2), c2 = cosf(lat2);
    const float sd = sinf(dlon), cd = cosf(dlon);

    // separately rounded, matching XLA's elementwise lowering
    float cosd = __fadd_rn(__fmul_rn(s1, s2),
                           __fmul_rn(__fmul_rn(c1, c2), cd));
    cosd = fminf(fmaxf(cosd, -1.0f + 1e-7f), 1.0f - 1e-7f);

    // exact +0 in the degenerate case -> atan2(+0,+0) = +0 like the reference
    const float yy = __fsub_rn(__fmul_rn(c1, s2),
                               __fmul_rn(__fmul_rn(s1, c2), cd));
    const float xx = __fmul_rn(sd, c2);

    g_dp[t] = make_float2(acosf(cosd), atan2f(xx, yy));
}

// ---------------- Kernel 2: weights + gather + store, one warp per node ----
__global__ __launch_bounds__(256) void project_kernel(
    const float* __restrict__ x,
    const float* __restrict__ sigma_d_p,
    const float* __restrict__ kappa_p,
    const int*   __restrict__ local_indices,
    const int*   __restrict__ adjc,
    float*       __restrict__ out,         // [N, 4, 8, 16]
    int N)
{
    const int warp = threadIdx.x >> 5;
    const int lane = threadIdx.x & 31;
    const int node = blockIdx.x * 8 + warp;
    if (node >= N) return;

    const int li   = __ldg(&local_indices[node]);
    const int base = node * 7;

    // warp-uniform loads -> L1 broadcast
    int    idx[7];
    float2 dp7[7];
#pragma unroll
    for (int k = 0; k < 7; k++) {
        idx[k] = __ldg(&adjc[li * 7 + k]);
        dp7[k] = __ldg(&g_dp[base + k]);
    }

    const float inv_sigma = 1.0f / __ldg(&sigma_d_p[0]);
    const float kappa     = __ldg(&kappa_p[0]);

    // this lane's (d, t) grid cell
    const int d_i = lane >> 3;
    const int t_i = lane & 7;
    const float dpos  = (float)d_i * (0.2f / 3.0f);          // linspace(0,0.2,4)
    const float theta = -PI_F + (float)t_i * (PI_F * 0.25f); // linspace(-pi,pi,9)[:-1]

    // fused fast-math weights: exp(kappa*cos(theta-phi) - z^2/2)
    float w[7];
    float sum = 0.0f;
#pragma unroll
    for (int k = 0; k < 7; k++) {
        const float z   = (dpos - dp7[k].x) * inv_sigma;
        const float arg = __fmaf_rn(kappa, __cosf(theta - dp7[k].y),
                                    -0.5f * z * z);
        w[k] = __expf(arg);
        sum += w[k];
    }
    const float inv = 1.0f / (sum + 1e-10f);

    // weighted feature sum (warp-uniform float4 gathers)
    float4 a0 = make_float4(0.f, 0.f, 0.f, 0.f);
    float4 a1 = a0, a2 = a0, a3 = a0;
#pragma unroll
    for (int k = 0; k < 7; k++) {
        const float wk = w[k] * inv;
        const float4* row = reinterpret_cast<const float4*>(x + (size_t)idx[k] * 16);
        const float4 v0 = __ldg(row + 0);
        const float4 v1 = __ldg(row + 1);
        const float4 v2 = __ldg(row + 2);
        const float4 v3 = __ldg(row + 3);
        a0.x += wk * v0.x; a0.y += wk * v0.y; a0.z += wk * v0.z; a0.w += wk * v0.w;
        a1.x += wk * v1.x; a1.y += wk * v1.y; a1.z += wk * v1.z; a1.w += wk * v1.w;
        a2.x += wk * v2.x; a2.y += wk * v2.y; a2.z += wk * v2.z; a2.w += wk * v2.w;
        a3.x += wk * v3.x; a3.y += wk * v3.y; a3.z += wk * v3.z; a3.w += wk * v3.w;
    }

    // coalesced contiguous write: out[node*512 + lane*16 .. +16]
    float* o = out + (size_t)node * 512 + (size_t)lane * 16;
    reinterpret_cast<float4*>(o)[0] = a0;
    reinterpret_cast<float4*>(o)[1] = a1;
    reinterpret_cast<float4*>(o)[2] = a2;
    reinterpret_cast<float4*>(o)[3] = a3;
}

extern "C" void kernel_launch(void* const* d_in, const int* in_sizes, int n_in,
                              void* d_out, int out_size) {
    const int N = out_size / 512;   // out is (1, N, 4, 8, 16)

    // Bind inputs by element count (robust to metadata ordering).
    const float* x       = 0;
    const float* coords  = 0;
    const float* sigma_d = 0;
    const float* kappa   = 0;
    const int*   lidx    = 0;
    const int*   adjc    = 0;
    int n_scalar = 0;
    for (int i = 0; i < n_in; i++) {
        const int s = in_sizes[i];
        if (s == 1) {
            if (n_scalar++ == 0) sigma_d = (const float*)d_in[i];
            else                 kappa   = (const float*)d_in[i];
        } else if (s == N)        lidx   = (const int*)d_in[i];
        else if (s == 2 * N)      coords = (const float*)d_in[i];
        else if (s == 7 * N)      adjc   = (const int*)d_in[i];
        else if (s == 16 * N)     x      = (const float*)d_in[i];
    }

    float* out = (float*)d_out;

    const int t1 = N * 7;
    trig_kernel<<<(t1 + 255) / 256, 256>>>(coords, lidx, adjc, N);
    project_kernel<<<(N + 7) / 8, 256>>>(x, sigma_d, kappa, lidx, adjc, out, N);
}

// round 12
// speedup vs baseline: 1.3738x; 1.2168x over previous
#include <cuda_runtime.h>
#include <math.h>

// grid_layer, two kernels.
//  K1: per-(node,neighbor) great-circle (dist,phi), precise separately-rounded
//      math (degenerate self-pair must give atan2(+0,+0)=+0 to match XLA).
//  K2: one warp per node. R7 lesson: warp-uniform LDG.128 does NOT dedupe
//      (4 wavefronts each) -> K2 was L1-bound. Now all per-node data is loaded
//      cooperatively (1-7 wavefronts total per array) and broadcast via
//      smem/LDS (broadcast = conflict-free) or shfl.

#define PI_F 3.14159265358979323846f
#define FULL 0xffffffffu
#define MAXN 65536

__device__ float2 g_dp[MAXN * 7];   // (dist, phi) per (node, neighbor)

// ---------------- Kernel 1: precise trig, one thread per (node, k) ----------
__global__ __launch_bounds__(256) void trig_kernel(
    const float* __restrict__ coords,      // [2, N]
    const int*   __restrict__ local_indices,
    const int*   __restrict__ adjc,        // [N, 7]
    int N)
{
    const int t = blockIdx.x * 256 + threadIdx.x;
    if (t >= N * 7) return;
    const int node = t / 7;
    const int k    = t - node * 7;

    const int li   = __ldg(&local_indices[node]);
    const int idx0 = __ldg(&adjc[li * 7]);
    const int idxk = __ldg(&adjc[li * 7 + k]);

    const float lon1 = __ldg(&coords[idx0]);
    const float lat1 = __ldg(&coords[N + idx0]);
    const float lon2 = __ldg(&coords[idxk]);
    const float lat2 = __ldg(&coords[N + idxk]);
    const float dlon = lon2 - lon1;

    const float s1 = sinf(lat1), c1 = cosf(lat1);
    const float s2 = sinf(lat2), c2 = cosf(lat2);
    const float sd = sinf(dlon), cd = cosf(dlon);

    // separately rounded, matching XLA's elementwise lowering
    float cosd = __fadd_rn(__fmul_rn(s1, s2),
                           __fmul_rn(__fmul_rn(c1, c2), cd));
    cosd = fminf(fmaxf(cosd, -1.0f + 1e-7f), 1.0f - 1e-7f);

    const float yy = __fsub_rn(__fmul_rn(c1, s2),
                               __fmul_rn(__fmul_rn(s1, c2), cd));
    const float xx = __fmul_rn(sd, c2);

    g_dp[t] = make_float2(acosf(cosd), atan2f(xx, yy));
}

// ---------------- Kernel 2: weights + gather + store, one warp per node ----
__global__ __launch_bounds__(256) void project_kernel(
    const float* __restrict__ x,
    const float* __restrict__ sigma_d_p,
    const float* __restrict__ kappa_p,
    const int*   __restrict__ local_indices,
    const int*   __restrict__ adjc,
    float*       __restrict__ out,         // [N, 4, 8, 16]
    int N)
{
    __shared__ float xs[8][116];           // 7 rows x 16 feats (+pad), per warp

    const int warp = threadIdx.x >> 5;
    const int lane = threadIdx.x & 31;
    const int node = blockIdx.x * 8 + warp;
    if (node >= N) return;

    // --- neighbor indices: speculate li == node (load both in parallel) ---
    int idxk = 0;
    if (lane < 7) idxk = __ldg(&adjc[node * 7 + lane]);     // speculative
    const int li = __ldg(&local_indices[node]);
    if (li != node) {                                        // warp-uniform
        if (lane < 7) idxk = __ldg(&adjc[li * 7 + lane]);
    }

    // --- dist/phi: 56B contiguous -> lanes 0..13, 1 wavefront, then shfl ---
    float dpv = 0.0f;
    if (lane < 14) dpv = __ldg(reinterpret_cast<const float*>(g_dp) + node * 14 + lane);
    float dist[7], phi[7];
#pragma unroll
    for (int k = 0; k < 7; k++) {
        dist[k] = __shfl_sync(FULL, dpv, 2 * k);
        phi[k]  = __shfl_sync(FULL, dpv, 2 * k + 1);
    }

    // --- x rows: 28 lanes, one LDG.128 each (7x64B), stage to smem ---
    const int xi = __shfl_sync(FULL, idxk, lane >> 2);
    if (lane < 28) {
        const float4 v = __ldg(reinterpret_cast<const float4*>(
            x + (size_t)xi * 16) + (lane & 3));
        *reinterpret_cast<float4*>(&xs[warp][(lane >> 2) * 16 + (lane & 3) * 4]) = v;
    }
    __syncwarp();

    const float inv_sigma = 1.0f / __ldg(&sigma_d_p[0]);
    const float kappa     = __ldg(&kappa_p[0]);

    // this lane's (d, t) grid cell
    const int d_i = lane >> 3;
    const int t_i = lane & 7;
    const float dpos  = (float)d_i * (0.2f / 3.0f);          // linspace(0,0.2,4)
    const float theta = -PI_F + (float)t_i * (PI_F * 0.25f); // linspace(-pi,pi,9)[:-1]

    // fused fast-math weights: exp(kappa*cos(theta-phi) - z^2/2)
    float w[7];
    float sum = 0.0f;
#pragma unroll
    for (int k = 0; k < 7; k++) {
        const float z   = (dpos - dist[k]) * inv_sigma;
        const float arg = __fmaf_rn(kappa, __cosf(theta - phi[k]),
                                    -0.5f * z * z);
        w[k] = __expf(arg);
        sum += w[k];
    }
    const float inv = 1.0f / (sum + 1e-10f);

    // weighted feature sum: broadcast LDS.128 (conflict-free) + FMA
    float4 a0 = make_float4(0.f, 0.f, 0.f, 0.f);
    float4 a1 = a0, a2 = a0, a3 = a0;
    const float* xw = xs[warp];
#pragma unroll
    for (int k = 0; k < 7; k++) {
        const float wk = w[k] * inv;
        const float4 v0 = *reinterpret_cast<const float4*>(xw + k * 16 + 0);
        const float4 v1 = *reinterpret_cast<const float4*>(xw + k * 16 + 4);
        const float4 v2 = *reinterpret_cast<const float4*>(xw + k * 16 + 8);
        const float4 v3 = *reinterpret_cast<const float4*>(xw + k * 16 + 12);
        a0.x += wk * v0.x; a0.y += wk * v0.y; a0.z += wk * v0.z; a0.w += wk * v0.w;
        a1.x += wk * v1.x; a1.y += wk * v1.y; a1.z += wk * v1.z; a1.w += wk * v1.w;
        a2.x += wk * v2.x; a2.y += wk * v2.y; a2.z += wk * v2.z; a2.w += wk * v2.w;
        a3.x += wk * v3.x; a3.y += wk * v3.y; a3.z += wk * v3.z; a3.w += wk * v3.w;
    }

    // coalesced contiguous write: out[node*512 + lane*16 .. +16]
    float* o = out + (size_t)node * 512 + (size_t)lane * 16;
    reinterpret_cast<float4*>(o)[0] = a0;
    reinterpret_cast<float4*>(o)[1] = a1;
    reinterpret_cast<float4*>(o)[2] = a2;
    reinterpret_cast<float4*>(o)[3] = a3;
}

extern "C" void kernel_launch(void* const* d_in, const int* in_sizes, int n_in,
                              void* d_out, int out_size) {
    const int N = out_size / 512;   // out is (1, N, 4, 8, 16)

    // Bind inputs by element count (robust to metadata ordering).
    const float* x       = 0;
    const float* coords  = 0;
    const float* sigma_d = 0;
    const float* kappa   = 0;
    const int*   lidx    = 0;
    const int*   adjc    = 0;
    int n_scalar = 0;
    for (int i = 0; i < n_in; i++) {
        const int s = in_sizes[i];
        if (s == 1) {
            if (n_scalar++ == 0) sigma_d = (const float*)d_in[i];
            else                 kappa   = (const float*)d_in[i];
        } else if (s == N)        lidx   = (const int*)d_in[i];
        else if (s == 2 * N)      coords = (const float*)d_in[i];
        else if (s == 7 * N)      adjc   = (const int*)d_in[i];
        else if (s == 16 * N)     x      = (const float*)d_in[i];
    }

    float* out = (float*)d_out;

    const int t1 = N * 7;
    trig_kernel<<<(t1 + 255) / 256, 256>>>(coords, lidx, adjc, N);
    project_kernel<<<(N + 7) / 8, 256>>>(x, sigma_d, kappa, lidx, adjc, out, N);
}